// round 2
// baseline (speedup 1.0000x reference)
#include <cuda_runtime.h>
#include <math.h>

// Problem constants
#define N_TOK 8192
#define HDIM  2048
#define TDIM  256
#define RDIM  512
#define NE    16

// ---------------- scratch (device globals: no allocation allowed) ----------------
__device__ float g_distilled[N_TOK * TDIM];          // 8 MB
__device__ float g_cnorm[NE * TDIM];                 // normalized centroids
__device__ float g_pstar[N_TOK];
__device__ int   g_estar[N_TOK];
__device__ int   g_counts[NE];
__device__ int   g_offsets[NE + 1];
__device__ int   g_cursor[NE];
__device__ int   g_tok[N_TOK];                       // token ids grouped by expert
__device__ float g_hmid[N_TOK * RDIM];               // 16 MB, gelu(premise@Wd), segment order

__device__ __forceinline__ float gelu_exact(float x) {
    return 0.5f * x * (1.0f + erff(x * 0.70710678118654752f));
}

// ---------------- tiny setup kernels ----------------
__global__ void init_k() {
    if (threadIdx.x < NE) g_counts[threadIdx.x] = 0;
}

__global__ void centroid_norm_k(const float* __restrict__ centroids) {
    int e = blockIdx.x;
    int t = threadIdx.x;                 // 256 == TDIM
    float v = centroids[e * TDIM + t];
    __shared__ float red[TDIM];
    red[t] = v * v;
    __syncthreads();
    for (int s = 128; s > 0; s >>= 1) {
        if (t < s) red[t] += red[t + s];
        __syncthreads();
    }
    float n = sqrtf(red[0]);
    g_cnorm[e * TDIM + t] = v / fmaxf(n, 1e-8f);
}

// One warp per token: l2norm, 16 cosine distances, softmax(-dist), top-2,
// e* = max(top-2 indices), p* = its softmax prob (reference's assign-last trick).
__global__ void router_post_k() {
    int warp = threadIdx.x >> 5;
    int lane = threadIdx.x & 31;
    int token = blockIdx.x * 8 + warp;
    const float* drow = g_distilled + (size_t)token * TDIM;
    float v[8];
    float ss = 0.f;
#pragma unroll
    for (int j = 0; j < 8; j++) { v[j] = drow[j * 32 + lane]; ss += v[j] * v[j]; }
#pragma unroll
    for (int o = 16; o > 0; o >>= 1) ss += __shfl_xor_sync(0xffffffffu, ss, o);
    float inv = 1.f / fmaxf(sqrtf(ss), 1e-8f);

    float neg[NE];
    float mx = -1e30f;
#pragma unroll
    for (int e = 0; e < NE; e++) {
        const float* crow = g_cnorm + e * TDIM;
        float dd = 0.f;
#pragma unroll
        for (int j = 0; j < 8; j++) dd += v[j] * crow[j * 32 + lane];
#pragma unroll
        for (int o = 16; o > 0; o >>= 1) dd += __shfl_xor_sync(0xffffffffu, dd, o);
        float cosv = dd * inv;
        float dist = sqrtf(fmaxf(2.f - 2.f * cosv, 0.f));
        neg[e] = -dist;
        mx = fmaxf(mx, neg[e]);
    }
    float sum = 0.f;
#pragma unroll
    for (int e = 0; e < NE; e++) sum += expf(neg[e] - mx);

    // top-2 by prob == top-2 by neg (softmax monotone); ties -> lowest index (matches top_k)
    int i1 = 0; float b1 = neg[0];
#pragma unroll
    for (int e = 1; e < NE; e++) if (neg[e] > b1) { b1 = neg[e]; i1 = e; }
    int i2 = (i1 == 0) ? 1 : 0; float b2 = neg[i2];
#pragma unroll
    for (int e = 0; e < NE; e++) if (e != i1 && neg[e] > b2) { b2 = neg[e]; i2 = e; }
    int estar = (i1 > i2) ? i1 : i2;
    float pstar = expf(neg[estar] - mx) / sum;

    if (lane == 0) {
        g_estar[token] = estar;
        g_pstar[token] = pstar;
        atomicAdd(&g_counts[estar], 1);
    }
}

__global__ void scan_k() {
    if (threadIdx.x == 0) {
        int run = 0;
        for (int e = 0; e < NE; e++) {
            g_offsets[e] = run;
            g_cursor[e]  = run;
            run += g_counts[e];
        }
        g_offsets[NE] = run;
    }
}

__global__ void scatter_k() {
    int n = blockIdx.x * blockDim.x + threadIdx.x;
    if (n < N_TOK) {
        int e = g_estar[n];
        int pos = atomicAdd(&g_cursor[e], 1);
        g_tok[pos] = n;
    }
}

// ---------------- fp32 tiled GEMM core: 128x128x16, 256 thr, 8x8/thread ----------------
// MODE 0: distilled = gelu(premise @ Wdist + bdist)            [N,T]
// MODE 1: hmid      = gelu(gather(premise) @ Wd[e])            [cnt,R]  (segment order)
// MODE 2: FUSED: acc1 = hmid_seg @ Wu[e] (K=512)
//               acc2 = gather(premise) @ Wg[e] (K=2048)
//         out[t] = p*[t] * ( sig(acc2+bg) * acc1 + (1-sig)*premise[t] )
template<int MODE, int KDIM, int NCOLS>
__global__ void __launch_bounds__(256)
gemm_k(const float* __restrict__ premise,
       const float* __restrict__ Wbase,       // MODE2: Wu base
       const float* __restrict__ biasBase,    // MODE0: bdist, MODE2: bg
       const float* __restrict__ W2base,      // MODE2: Wg base
       float* __restrict__ outp)
{
    constexpr int BM = 128, BN = 128, BK = 16;
    const int e = (MODE == 0) ? 0 : blockIdx.z;
    int seg, cnt;
    if (MODE == 0) { seg = 0; cnt = N_TOK; }
    else { seg = g_offsets[e]; cnt = g_offsets[e + 1] - seg; }
    const int mtile = blockIdx.y * BM;
    if (mtile >= cnt) return;
    const int ntile = blockIdx.x * BN;

    __shared__ float As[BK][BM];
    __shared__ float Bs[BK][BN];

    const int tid  = threadIdx.x;
    const int tcol = tid & 15;
    const int trow = tid >> 4;

    // gathered premise row pointers (per loader thread, 2 fragments)
    const float* pRow[2];
#pragma unroll
    for (int i = 0; i < 2; i++) {
        int f  = tid + i * 256;
        int ar = f >> 2;
        int gm = mtile + ar;
        int row;
        if (MODE == 0)       row = gm;
        else                 row = g_tok[seg + ((gm < cnt) ? gm : 0)];
        pRow[i] = premise + (size_t)row * HDIM;
    }

    float acc[8][8];
#pragma unroll
    for (int i = 0; i < 8; i++)
#pragma unroll
        for (int j = 0; j < 8; j++) acc[i][j] = 0.f;

    // ---------- phase A ----------
    // MODE 0/1: A = premise rows, K = KDIM (2048), B = Wdist / Wd[e]
    // MODE 2:   A = hmid segment rows, K = RDIM (512), B = Wu[e]
    {
        const int KA = (MODE == 2) ? RDIM : KDIM;
        const float* __restrict__ B = Wbase + (size_t)e * KA * NCOLS + ntile;
        const float* aP[2];
#pragma unroll
        for (int i = 0; i < 2; i++) {
            if (MODE == 2) {
                int f = tid + i * 256;
                int ar = f >> 2;
                int gm = mtile + ar;
                int row = (gm < cnt) ? gm : (cnt - 1);
                aP[i] = g_hmid + (size_t)(seg + row) * RDIM;
            } else {
                aP[i] = pRow[i];
            }
        }
        for (int k0 = 0; k0 < KA; k0 += BK) {
#pragma unroll
            for (int i = 0; i < 2; i++) {
                int f = tid + i * 256;
                int ar = f >> 2, ac4 = f & 3;
                float4 v = *reinterpret_cast<const float4*>(aP[i] + k0 + ac4 * 4);
                As[ac4 * 4 + 0][ar] = v.x;
                As[ac4 * 4 + 1][ar] = v.y;
                As[ac4 * 4 + 2][ar] = v.z;
                As[ac4 * 4 + 3][ar] = v.w;
            }
#pragma unroll
            for (int i = 0; i < 2; i++) {
                int f = tid + i * 256;
                int br = f >> 5, bc4 = f & 31;
                float4 v = *reinterpret_cast<const float4*>(B + (size_t)(k0 + br) * NCOLS + bc4 * 4);
                *reinterpret_cast<float4*>(&Bs[br][bc4 * 4]) = v;
            }
            __syncthreads();
#pragma unroll
            for (int k = 0; k < BK; k++) {
                float ra[8], rb[8];
#pragma unroll
                for (int i = 0; i < 8; i++) ra[i] = As[k][trow * 8 + i];
#pragma unroll
                for (int j = 0; j < 8; j++) rb[j] = Bs[k][tcol * 8 + j];
#pragma unroll
                for (int i = 0; i < 8; i++)
#pragma unroll
                    for (int j = 0; j < 8; j++)
                        acc[i][j] = fmaf(ra[i], rb[j], acc[i][j]);
            }
            __syncthreads();
        }
    }

    if (MODE != 2) {
        // epilogue for MODE 0 / MODE 1
#pragma unroll
        for (int i = 0; i < 8; i++) {
            int gm = mtile + trow * 8 + i;
            if (gm >= cnt) continue;
#pragma unroll
            for (int j = 0; j < 8; j++) {
                int col = ntile + tcol * 8 + j;
                float v = acc[i][j];
                if (MODE == 0) {
                    g_distilled[(size_t)gm * NCOLS + col] = gelu_exact(v + biasBase[col]);
                } else {
                    g_hmid[(size_t)(seg + gm) * NCOLS + col] = gelu_exact(v);
                }
            }
        }
        return;
    }

    // ---------- phase B (MODE 2 only): gate GEMM, K = HDIM over gathered premise ----------
    float acc2[8][8];
#pragma unroll
    for (int i = 0; i < 8; i++)
#pragma unroll
        for (int j = 0; j < 8; j++) acc2[i][j] = 0.f;

    {
        const float* __restrict__ B = W2base + (size_t)e * HDIM * NCOLS + ntile;
        for (int k0 = 0; k0 < HDIM; k0 += BK) {
#pragma unroll
            for (int i = 0; i < 2; i++) {
                int f = tid + i * 256;
                int ar = f >> 2, ac4 = f & 3;
                float4 v = *reinterpret_cast<const float4*>(pRow[i] + k0 + ac4 * 4);
                As[ac4 * 4 + 0][ar] = v.x;
                As[ac4 * 4 + 1][ar] = v.y;
                As[ac4 * 4 + 2][ar] = v.z;
                As[ac4 * 4 + 3][ar] = v.w;
            }
#pragma unroll
            for (int i = 0; i < 2; i++) {
                int f = tid + i * 256;
                int br = f >> 5, bc4 = f & 31;
                float4 v = *reinterpret_cast<const float4*>(B + (size_t)(k0 + br) * NCOLS + bc4 * 4);
                *reinterpret_cast<float4*>(&Bs[br][bc4 * 4]) = v;
            }
            __syncthreads();
#pragma unroll
            for (int k = 0; k < BK; k++) {
                float ra[8], rb[8];
#pragma unroll
                for (int i = 0; i < 8; i++) ra[i] = As[k][trow * 8 + i];
#pragma unroll
                for (int j = 0; j < 8; j++) rb[j] = Bs[k][tcol * 8 + j];
#pragma unroll
                for (int i = 0; i < 8; i++)
#pragma unroll
                    for (int j = 0; j < 8; j++)
                        acc2[i][j] = fmaf(ra[i], rb[j], acc2[i][j]);
            }
            __syncthreads();
        }
    }

    // fused epilogue: gate, highway, scale, scatter to d_out
#pragma unroll
    for (int i = 0; i < 8; i++) {
        int gm = mtile + trow * 8 + i;
        if (gm >= cnt) continue;
        int t = g_tok[seg + gm];
        float ps = g_pstar[t];
#pragma unroll
        for (int j = 0; j < 8; j++) {
            int col = ntile + tcol * 8 + j;
            float gate = 1.f / (1.f + expf(-(acc2[i][j] + biasBase[(size_t)e * NCOLS + col])));
            float pv = premise[(size_t)t * HDIM + col];
            float y  = gate * acc[i][j] + (1.f - gate) * pv;
            outp[(size_t)t * HDIM + col] = ps * y;
        }
    }
}

// ---------------- launch ----------------
extern "C" void kernel_launch(void* const* d_in, const int* in_sizes, int n_in,
                              void* d_out, int out_size) {
    const float* premise   = (const float*)d_in[0];
    const float* Wdist     = (const float*)d_in[1];
    const float* bdist     = (const float*)d_in[2];
    const float* centroids = (const float*)d_in[3];
    const float* Wd        = (const float*)d_in[4];
    const float* Wu        = (const float*)d_in[5];
    const float* Wg        = (const float*)d_in[6];
    const float* bg        = (const float*)d_in[7];
    float* out = (float*)d_out;
    (void)in_sizes; (void)n_in; (void)out_size;   // k is fixed at 2

    init_k<<<1, 32>>>();
    centroid_norm_k<<<NE, TDIM>>>(centroids);

    // Router GEMM: [8192 x 256], K=2048, + bias + gelu
    gemm_k<0, HDIM, TDIM><<<dim3(TDIM / 128, N_TOK / 128, 1), 256>>>(premise, Wdist, bdist, nullptr, nullptr);

    router_post_k<<<N_TOK / 8, 256>>>();
    scan_k<<<1, 32>>>();
    scatter_k<<<N_TOK / 256, 256>>>();

    // Expert GEMM 1: hmid = gelu(gather(premise) @ Wd[e])  [cnt x 512]
    gemm_k<1, HDIM, RDIM><<<dim3(RDIM / 128, N_TOK / 128, NE), 256>>>(premise, Wd, nullptr, nullptr, nullptr);
    // Expert GEMM 2+3 fused: up-proj + gate + combine -> d_out  [cnt x 2048]
    gemm_k<2, HDIM, HDIM><<<dim3(HDIM / 128, N_TOK / 128, NE), 256>>>(premise, Wu, bg, Wg, out);
}